// round 1
// baseline (speedup 1.0000x reference)
#include <cuda_runtime.h>
#include <cstdint>

// TaylorExp: out[row] = [1, x/sqrt(sqrt(d)), (x_i*x_j)/(sqrt(2)*sqrt(d))]
// d = 16 -> per-row output = 1 + 16 + 256 = 273 floats.
// rows = in_sizes[0] / 16.
//
// One warp per row. Lanes 0..15 hold x in registers; broadcast via shfl.
// 9 coalesced 32-wide store sweeps per row (last covers 17 elements).

#define D 16
#define OUT_PER_ROW 273
#define FULL 0xffffffffu

__global__ void taylor_exp_kernel(const float* __restrict__ x,
                                  float* __restrict__ out,
                                  int rows) {
    const int gwarp = (blockIdx.x * blockDim.x + threadIdx.x) >> 5;
    const int lane  = threadIdx.x & 31;
    if (gwarp >= rows) return;

    // Coalesced row load: lanes 0..15 fetch one float each.
    float xv = 0.0f;
    if (lane < D) xv = x[(size_t)gwarp * D + lane];

    const float s_lin  = 0.5f;                    // 1/sqrt(sqrt(16)) = 1/2
    const float s_quad = 0.17677669529663689f;    // 1/(sqrt(2)*sqrt(16))

    float* o = out + (size_t)gwarp * OUT_PER_ROW;

    #pragma unroll
    for (int it = 0; it < 9; ++it) {
        const int idx = it * 32 + lane;

        // All shuffles unconditional, full mask (indices wrapped into 0..15;
        // garbage lanes are masked out by the predicated store / selects).
        const int k = idx - 17;                     // quadratic flat index
        const float xl = __shfl_sync(FULL, xv, (idx - 1) & 15); // linear term src
        const float xi = __shfl_sync(FULL, xv, (k >> 4) & 15);
        const float xj = __shfl_sync(FULL, xv, k & 15);

        float v = xi * xj * s_quad;
        if (idx < 17) v = xl * s_lin;
        if (idx == 0) v = 1.0f;

        if (idx < OUT_PER_ROW) o[idx] = v;
    }
}

extern "C" void kernel_launch(void* const* d_in, const int* in_sizes, int n_in,
                              void* d_out, int out_size) {
    const float* x = (const float*)d_in[0];
    float* out = (float*)d_out;

    const int rows = in_sizes[0] / D;   // 262144 for the bench shape

    const int threads = 256;            // 8 warps/block
    const int warps_per_block = threads / 32;
    const int blocks = (rows + warps_per_block - 1) / warps_per_block;

    taylor_exp_kernel<<<blocks, threads>>>(x, out, rows);
}